// round 6
// baseline (speedup 1.0000x reference)
#include <cuda_runtime.h>
#include <cstdint>

// RBDispatcher: two-stage gather + concat, fully fused.
//   out[r]        = x[ idx_s1[ s1_to_s2[r] ] / TOP_K ]   for r in [0, N_S2)
//   out[N_S2 + r] = x[ idx_s1[r] / TOP_K ]               for r in [0, N_S1)
//
// Indices are int32 on device (JAX demotes int64 without x64).
//
// R5: persistent CTAs + software pipeline. R4 showed 4x per-thread MLP was
// neutral (42.5->42.1us, DRAM 66%): tiny one-shot CTAs (4 LDG + 4 STG then
// exit) across 10+ waves kept draining the in-flight pool. Now 1184
// persistent CTAs grid-stride over rows, prefetching iteration i+1's loads
// before storing iteration i -> loads continuously in flight, no CTA churn,
// no wave tail.

static constexpr int D_MODEL = 2048;
static constexpr int TOP_K   = 2;
static constexpr int VECS    = D_MODEL / 4;   // 512 float4 per row
static constexpr int NT      = 256;           // threads per block
static constexpr int ROWS_PER_IT = 2;
static constexpr int N_CTAS  = 148 * 8;       // one full resident wave

__device__ __forceinline__ int compose_idx(const int* __restrict__ idx_s1,
                                           const int* __restrict__ s1_to_s2,
                                           int row, int n_s2)
{
    int e = (row < n_s2) ? idx_s1[s1_to_s2[row]] : idx_s1[row - n_s2];
    return e / TOP_K;
}

__global__ __launch_bounds__(NT, 8)
void rb_dispatch_kernel(const float4* __restrict__ x,
                        const int* __restrict__ idx_s1,
                        const int* __restrict__ s1_to_s2,
                        float4* __restrict__ out,
                        int n_s2, int n_rows)
{
    const int t = threadIdx.x;
    const int stride = gridDim.x * ROWS_PER_IT;

    int row = blockIdx.x * ROWS_PER_IT;
    if (row >= n_rows) return;

    // ---- prologue: load iteration 0 ----
    int s0 = compose_idx(idx_s1, s1_to_s2, row,     n_s2);
    int s1 = compose_idx(idx_s1, s1_to_s2, row + 1, n_s2);
    const float4* p0 = x + (long long)s0 * VECS;
    const float4* p1 = x + (long long)s1 * VECS;
    float4 a0 = __ldg(&p0[t]);
    float4 a1 = __ldg(&p0[t + NT]);
    float4 b0 = __ldg(&p1[t]);
    float4 b1 = __ldg(&p1[t + NT]);

    for (;;) {
        const int next = row + stride;
        float4 c0, c1, d0, d1;
        const bool more = (next < n_rows);
        if (more) {
            // Issue next iteration's loads BEFORE this iteration's stores:
            // keeps ~8 independent LDG.128/thread in flight continuously.
            int ns0 = compose_idx(idx_s1, s1_to_s2, next,     n_s2);
            int ns1 = compose_idx(idx_s1, s1_to_s2, next + 1, n_s2);
            const float4* q0 = x + (long long)ns0 * VECS;
            const float4* q1 = x + (long long)ns1 * VECS;
            c0 = __ldg(&q0[t]);
            c1 = __ldg(&q0[t + NT]);
            d0 = __ldg(&q1[t]);
            d1 = __ldg(&q1[t + NT]);
        }

        // Streaming stores (evict-first) keep x L2-resident -> reads ~90%
        // L2-hit, DRAM bill is writes only.
        float4* o0 = out + (long long)row * VECS;
        float4* o1 = o0 + VECS;
        __stcs(&o0[t],      a0);
        __stcs(&o0[t + NT], a1);
        __stcs(&o1[t],      b0);
        __stcs(&o1[t + NT], b1);

        if (!more) break;
        a0 = c0; a1 = c1; b0 = d0; b1 = d1;
        row = next;
    }
}

extern "C" void kernel_launch(void* const* d_in, const int* in_sizes, int n_in,
                              void* d_out, int out_size)
{
    const float4* x        = (const float4*)d_in[0];
    const int*    idx_s1   = (const int*)d_in[1];
    const int*    s1_to_s2 = (const int*)d_in[2];

    const int n_s1 = in_sizes[1];        // 16384
    const int n_s2 = in_sizes[2];        // 8192
    const int n_rows = n_s1 + n_s2;      // 24576 (even)

    int n_ctas = N_CTAS;
    const int max_ctas = n_rows / ROWS_PER_IT;
    if (n_ctas > max_ctas) n_ctas = max_ctas;

    rb_dispatch_kernel<<<n_ctas, NT>>>(
        x, idx_s1, s1_to_s2, (float4*)d_out, n_s2, n_rows);
}

// round 8
// speedup vs baseline: 1.0785x; 1.0785x over previous
#include <cuda_runtime.h>
#include <cstdint>

// RBDispatcher: two-stage gather + concat, fully fused.
//   out[r]        = x[ idx_s1[ s1_to_s2[r] ] / TOP_K ]   for r in [0, N_S2)
//   out[N_S2 + r] = x[ idx_s1[r] / TOP_K ]               for r in [0, N_S1)
//
// Indices are int32 on device (JAX demotes int64 without x64).
//
// R7: keep the best structure (R4: one-shot 2-rows/block, 42.1us) and add
// source dedup. indices_s1 is SORTED, so the paired rows (2b, 2b+1) in the
// s1 half share the same source row ~50% of the time (16384 sorted draws /
// top_k -> 8192 tokens, ~2 slots/token). When s0==s1, load the row ONCE and
// store it to both destinations from registers -> ~25% less s1-half read
// traffic through LTS (the suspected ceiling; schedule changes R3/R4/R5 were
// all neutral at ~5.2TB/s).

static constexpr int D_MODEL = 2048;
static constexpr int TOP_K   = 2;
static constexpr int VECS    = D_MODEL / 4;   // 512 float4 per row
static constexpr int NT      = 256;           // threads per block
static constexpr int ROWS_PER_BLK = 2;

__global__ __launch_bounds__(NT, 8)
void rb_dispatch_kernel(const float4* __restrict__ x,
                        const int* __restrict__ idx_s1,
                        const int* __restrict__ s1_to_s2,
                        float4* __restrict__ out,
                        int n_s2)
{
    const int row0 = blockIdx.x * ROWS_PER_BLK;
    const int row1 = row0 + 1;
    const int t = threadIdx.x;

    // Compose gather indices (uniform loads, broadcast through L1).
    int e0 = (row0 < n_s2) ? idx_s1[s1_to_s2[row0]] : idx_s1[row0 - n_s2];
    int e1 = (row1 < n_s2) ? idx_s1[s1_to_s2[row1]] : idx_s1[row1 - n_s2];
    const int s0 = e0 / TOP_K;
    const int s1 = e1 / TOP_K;

    float4* __restrict__ dst0 = out + (long long)row0 * VECS;
    float4* __restrict__ dst1 = dst0 + VECS;

    const float4* __restrict__ src0 = x + (long long)s0 * VECS;

    if (s0 == s1) {
        // Duplicate source (common in the sorted s1 half): one read, two
        // writes, straight from registers.
        float4 a0 = __ldg(&src0[t]);
        float4 a1 = __ldg(&src0[t + NT]);
        __stcs(&dst0[t],      a0);
        __stcs(&dst0[t + NT], a1);
        __stcs(&dst1[t],      a0);
        __stcs(&dst1[t + NT], a1);
    } else {
        const float4* __restrict__ src1 = x + (long long)s1 * VECS;
        // Batch all 4 loads, then all 4 stores (R4's proven pattern).
        float4 a0 = __ldg(&src0[t]);
        float4 a1 = __ldg(&src0[t + NT]);
        float4 b0 = __ldg(&src1[t]);
        float4 b1 = __ldg(&src1[t + NT]);
        // Streaming stores: evict-first keeps x (64 MiB) L2-resident, so
        // reads stay ~90% L2-hit and the DRAM bill is writes only.
        __stcs(&dst0[t],      a0);
        __stcs(&dst0[t + NT], a1);
        __stcs(&dst1[t],      b0);
        __stcs(&dst1[t + NT], b1);
    }
}

extern "C" void kernel_launch(void* const* d_in, const int* in_sizes, int n_in,
                              void* d_out, int out_size)
{
    const float4* x        = (const float4*)d_in[0];
    const int*    idx_s1   = (const int*)d_in[1];
    const int*    s1_to_s2 = (const int*)d_in[2];

    const int n_s1 = in_sizes[1];        // 16384
    const int n_s2 = in_sizes[2];        // 8192
    const int n_out_rows = n_s1 + n_s2;  // 24576 (even)

    rb_dispatch_kernel<<<n_out_rows / ROWS_PER_BLK, NT>>>(
        x, idx_s1, s1_to_s2, (float4*)d_out, n_s2);
}